// round 4
// baseline (speedup 1.0000x reference)
#include <cuda_runtime.h>

#define U   2048
#define BSZ 16
#define DK  32
#define TM  128
#define TN  128
#define NTILES (U / TM)   // 16

// Scratch (static __device__ — no allocation allowed)
__device__ float g_rowsum[6][BSZ][U];              // directed row sums: 0:(A,V) 1:(V,A) 2:(A,L) 3:(L,A) 4:(V,L) 5:(L,V)
__device__ float g_colpart[3][BSZ][NTILES][U];     // per-row-tile partial column sums (25.2 MB)
__device__ float g_Bi[BSZ][3][64];                 // Bi rows
__device__ float g_row[BSZ][64];                   // final per-batch CCA row

// ---------------------------------------------------------------------------
// Kernel 1: fused gram + exp + dual reduction.
// grid = (row_tile, batch, pair). Each CTA: 128 rows of X vs all 2048 rows of Y.
// Produces exact rowsum(X,Y) for its rows and partial rowsum(Y,X) (col sums).
// ---------------------------------------------------------------------------
__global__ __launch_bounds__(256) void gram_kernel(const float* __restrict__ A,
                                                   const float* __restrict__ V,
                                                   const float* __restrict__ L)
{
    const int tileR = blockIdx.x;
    const int b     = blockIdx.y;
    const int p     = blockIdx.z;

    const float *X, *Y;
    if (p == 0)      { X = A; Y = V; }
    else if (p == 1) { X = A; Y = L; }
    else             { X = V; Y = L; }
    X += (size_t)b * U * DK;
    Y += (size_t)b * U * DK;

    __shared__ float Xs[DK][TM];        // k-major for conflict-free outer-product reads
    __shared__ float Ys[DK][TN];
    __shared__ float red[16][TN + 8];   // reduction scratch

    const int tid = threadIdx.x;
    const int tx  = tid & 15;
    const int ty  = tid >> 4;

    // Load this CTA's X row tile (transpose to k-major)
    for (int idx = tid; idx < TM * 8; idx += 256) {
        int r  = idx >> 3;
        int kq = (idx & 7) * 4;
        float4 v4 = *(const float4*)&X[(size_t)(tileR * TM + r) * DK + kq];
        Xs[kq + 0][r] = v4.x; Xs[kq + 1][r] = v4.y;
        Xs[kq + 2][r] = v4.z; Xs[kq + 3][r] = v4.w;
    }

    float row_acc[8];
#pragma unroll
    for (int i = 0; i < 8; i++) row_acc[i] = 0.f;

    for (int tc = 0; tc < NTILES; tc++) {
        __syncthreads();   // previous iter's Ys / red consumers done
        for (int idx = tid; idx < TN * 8; idx += 256) {
            int r  = idx >> 3;
            int kq = (idx & 7) * 4;
            float4 v4 = *(const float4*)&Y[(size_t)(tc * TN + r) * DK + kq];
            Ys[kq + 0][r] = v4.x; Ys[kq + 1][r] = v4.y;
            Ys[kq + 2][r] = v4.z; Ys[kq + 3][r] = v4.w;
        }
        __syncthreads();

        float acc[8][8];
#pragma unroll
        for (int i = 0; i < 8; i++)
#pragma unroll
            for (int c = 0; c < 8; c++) acc[i][c] = 0.f;

#pragma unroll 8
        for (int k = 0; k < DK; k++) {
            float xa[8], yb[8];
#pragma unroll
            for (int i = 0; i < 8; i++) xa[i] = Xs[k][ty * 8 + i];
#pragma unroll
            for (int c = 0; c < 8; c++) yb[c] = Ys[k][tx * 8 + c];
#pragma unroll
            for (int i = 0; i < 8; i++)
#pragma unroll
                for (int c = 0; c < 8; c++)
                    acc[i][c] = fmaf(xa[i], yb[c], acc[i][c]);
        }

        // exp once, feed both reductions (no max needed: |dot| <= ~40 -> fp32-safe)
        float cp[8];
#pragma unroll
        for (int c = 0; c < 8; c++) cp[c] = 0.f;
#pragma unroll
        for (int i = 0; i < 8; i++)
#pragma unroll
            for (int c = 0; c < 8; c++) {
                float e = __expf(acc[i][c]);
                row_acc[i] += e;
                cp[c]      += e;
            }

        // reduce column partials over ty, write this tile's 128 columns
#pragma unroll
        for (int c = 0; c < 8; c++) red[ty][tx * 8 + c] = cp[c];
        __syncthreads();
        if (tid < TN) {
            float s = 0.f;
#pragma unroll
            for (int t = 0; t < 16; t++) s += red[t][tid];
            g_colpart[p][b][tileR][tc * TN + tid] = s;
        }
    }

    // reduce row sums over tx
    __syncthreads();
#pragma unroll
    for (int i = 0; i < 8; i++) red[tx][ty * 8 + i] = row_acc[i];
    __syncthreads();
    if (tid < TM) {
        float s = 0.f;
#pragma unroll
        for (int t = 0; t < 16; t++) s += red[t][tid];
        g_rowsum[2 * p][b][tileR * TM + tid] = s;
    }
}

// ---------------------------------------------------------------------------
// Kernel 2: deterministic reduction of column-sum partials.
// ---------------------------------------------------------------------------
__global__ void reduce_colpart_kernel()
{
    int idx = blockIdx.x * 256 + threadIdx.x;
    if (idx >= 3 * BSZ * U) return;
    int j   = idx & (U - 1);
    int rem = idx / U;
    int b   = rem & (BSZ - 1);
    int p   = rem / BSZ;
    float s = 0.f;
#pragma unroll
    for (int t = 0; t < NTILES; t++) s += g_colpart[p][b][t][j];
    g_rowsum[2 * p + 1][b][j] = s;
}

// ---------------------------------------------------------------------------
// Kernel 3: finalize Bi rows. One CTA per (batch, pair).
// ---------------------------------------------------------------------------
__global__ __launch_bounds__(256) void finalize_kernel(const float* __restrict__ A,
                                                       const float* __restrict__ V,
                                                       const float* __restrict__ L)
{
    const int b = blockIdx.x;
    const int p = blockIdx.y;
    const float *X, *Y;
    if (p == 0)      { X = A; Y = V; }
    else if (p == 1) { X = A; Y = L; }
    else             { X = V; Y = L; }
    X += (size_t)b * U * DK;
    Y += (size_t)b * U * DK;

    __shared__ float X0[32], Y0[32];
    __shared__ float sred[8][64];

    const int tid = threadIdx.x;
    if (tid < 32)      X0[tid]      = X[tid];
    else if (tid < 64) Y0[tid - 32] = Y[tid - 32];
    __syncthreads();

    float O1[32], O2[32];
#pragma unroll
    for (int d = 0; d < 32; d++) { O1[d] = 0.f; O2[d] = 0.f; }

    for (int j = tid; j < U; j += 256) {
        float xj[32], yj[32];
#pragma unroll
        for (int q = 0; q < 8; q++) {
            float4 v = *(const float4*)&Y[(size_t)j * DK + q * 4];
            yj[q*4+0] = v.x; yj[q*4+1] = v.y; yj[q*4+2] = v.z; yj[q*4+3] = v.w;
            float4 w = *(const float4*)&X[(size_t)j * DK + q * 4];
            xj[q*4+0] = w.x; xj[q*4+1] = w.y; xj[q*4+2] = w.z; xj[q*4+3] = w.w;
        }
        float d1 = 0.f, d2 = 0.f;
#pragma unroll
        for (int k = 0; k < 32; k++) {
            d1 = fmaf(X0[k], yj[k], d1);   // f1_0 . f2_j
            d2 = fmaf(xj[k], Y0[k], d2);   // f1_j . f2_0
        }
        float w1 = __expf(d1) / g_rowsum[2 * p + 1][b][j];  // / colsum_j
        float w2 = __expf(d2) / g_rowsum[2 * p][b][j];      // / rowsum_j
#pragma unroll
        for (int k = 0; k < 32; k++) {
            O1[k] = fmaf(w1, yj[k], O1[k]);
            O2[k] = fmaf(w2, xj[k], O2[k]);
        }
    }

    // intra-warp reduce
#pragma unroll
    for (int k = 0; k < 32; k++) {
        for (int o = 16; o > 0; o >>= 1) {
            O1[k] += __shfl_down_sync(0xffffffffu, O1[k], o);
            O2[k] += __shfl_down_sync(0xffffffffu, O2[k], o);
        }
    }
    const int w    = tid >> 5;
    const int lane = tid & 31;
    if (lane == 0) {
#pragma unroll
        for (int k = 0; k < 32; k++) {
            sred[w][k]      = O1[k];
            sred[w][k + 32] = O2[k];
        }
    }
    __syncthreads();
    if (tid < 64) {
        float s = 0.f;
#pragma unroll
        for (int t = 0; t < 8; t++) s += sred[t][tid];
        float a = (tid < 32) ? X0[tid] : Y0[tid - 32];   // A1 = O1*f1_0 ; A2 = O2*f2_0
        g_Bi[b][p][tid] = s * a;
    }
}

// ---------------------------------------------------------------------------
// Kernel 4: FC head + batch-axis softmax + alpha-weighted combine (tiny).
// ---------------------------------------------------------------------------
__global__ void head_kernel(const float* __restrict__ fc1w,
                            const float* __restrict__ fc1b,
                            const float* __restrict__ fc2w)
{
    __shared__ float Ci[48];
    __shared__ float colsum[3];
    const int t = threadIdx.x;

    if (t < 48) {
        int b = t / 3, k = t % 3;
        const float* row = g_Bi[b][k];
        float ci = 0.f;
        for (int o = 0; o < 64; o++) {
            float h = fc1b[o];
#pragma unroll 8
            for (int m = 0; m < 64; m++) h = fmaf(row[m], fc1w[o * 64 + m], h);
            ci += tanhf(h) * fc2w[o];
        }
        Ci[t] = ci;
    }
    __syncthreads();
    if (t < 3) {
        float s = 0.f;
        for (int b = 0; b < 16; b++) s += expf(Ci[b * 3 + t]);
        colsum[t] = s;
    }
    __syncthreads();
    if (t < 64) {
        for (int b = 0; b < 16; b++) {
            float s = 0.f;
#pragma unroll
            for (int k = 0; k < 3; k++) {
                float alpha = expf(Ci[b * 3 + k]) / colsum[k];
                s += alpha * g_Bi[b][k][t];
            }
            g_row[b][t] = s;
        }
    }
}

// ---------------------------------------------------------------------------
// Kernel 5: broadcast per-batch row to [B, U, 64].
// ---------------------------------------------------------------------------
__global__ void bcast_kernel(float4* __restrict__ out)
{
    int i = blockIdx.x * 256 + threadIdx.x;      // float4 index
    if (i >= BSZ * U * 16) return;
    int d4  = i & 15;
    int u_b = i >> 4;
    int b   = u_b >> 11;                          // / 2048
    out[i] = ((const float4*)g_row)[b * 16 + d4];
}

// ---------------------------------------------------------------------------
extern "C" void kernel_launch(void* const* d_in, const int* in_sizes, int n_in,
                              void* d_out, int out_size)
{
    const float* A    = (const float*)d_in[0];
    const float* V    = (const float*)d_in[1];
    const float* L    = (const float*)d_in[2];
    const float* fc1w = (const float*)d_in[3];
    const float* fc1b = (const float*)d_in[4];
    const float* fc2w = (const float*)d_in[5];

    dim3 g1(NTILES, BSZ, 3);
    gram_kernel<<<g1, 256>>>(A, V, L);
    reduce_colpart_kernel<<<(3 * BSZ * U + 255) / 256, 256>>>();
    finalize_kernel<<<dim3(BSZ, 3), 256>>>(A, V, L);
    head_kernel<<<1, 64>>>(fc1w, fc1b, fc2w);
    bcast_kernel<<<(BSZ * U * 16 + 255) / 256, 256>>>((float4*)d_out);
}

// round 7
// speedup vs baseline: 1.1337x; 1.1337x over previous
#include <cuda_runtime.h>

#define U   2048
#define BSZ 16
#define DK  32
#define TM  128
#define TN  128
#define NTILES (U / TM)   // 16

typedef unsigned long long ull;

// Scratch (static __device__ — no allocation allowed)
__device__ float g_rowsum[6][BSZ][U];              // directed row sums
__device__ float g_colpart[3][BSZ][NTILES][U];     // per-row-tile partial column sums
__device__ float g_Bi[BSZ][3][64];                 // Bi rows
__device__ float g_row[BSZ][64];                   // final per-batch CCA row

// ---- packed f32x2 helpers (sm_103a) ---------------------------------------
__device__ __forceinline__ ull splat2(float x) {
    ull r; asm("mov.b64 %0, {%1, %1};" : "=l"(r) : "f"(x)); return r;
}
__device__ __forceinline__ ull pack2(float lo, float hi) {
    ull r; asm("mov.b64 %0, {%1, %2};" : "=l"(r) : "f"(lo), "f"(hi)); return r;
}
__device__ __forceinline__ void fma2(ull &d, ull a, ull b) {
    asm("fma.rn.f32x2 %0, %1, %2, %0;" : "+l"(d) : "l"(a), "l"(b));
}
__device__ __forceinline__ void unpack2(ull v, float &lo, float &hi) {
    asm("mov.b64 {%0, %1}, %2;" : "=f"(lo), "=f"(hi) : "l"(v));
}

// ---------------------------------------------------------------------------
// Kernel 1: fused gram + exp + dual reduction (FFMA2 mainloop).
// grid = (row_tile, batch, pair). Each CTA: 128 rows of X vs all 2048 of Y.
// ---------------------------------------------------------------------------
__global__ __launch_bounds__(256) void gram_kernel(const float* __restrict__ A,
                                                   const float* __restrict__ V,
                                                   const float* __restrict__ L)
{
    const int tileR = blockIdx.x;
    const int b     = blockIdx.y;
    const int p     = blockIdx.z;

    const float *X, *Y;
    if (p == 0)      { X = A; Y = V; }
    else if (p == 1) { X = A; Y = L; }
    else             { X = V; Y = L; }
    X += (size_t)b * U * DK;
    Y += (size_t)b * U * DK;

    __shared__ float Xs[DK][TM];        // k-major
    __shared__ float Ys[DK][TN];
    __shared__ float red[16][TN + 8];

    const int tid = threadIdx.x;
    const int tx  = tid & 15;
    const int ty  = tid >> 4;

    // Load X row tile (transpose to k-major)
    for (int idx = tid; idx < TM * 8; idx += 256) {
        int r  = idx >> 3;
        int kq = (idx & 7) * 4;
        float4 v4 = *(const float4*)&X[(size_t)(tileR * TM + r) * DK + kq];
        Xs[kq + 0][r] = v4.x; Xs[kq + 1][r] = v4.y;
        Xs[kq + 2][r] = v4.z; Xs[kq + 3][r] = v4.w;
    }

    float row_acc[8];
#pragma unroll
    for (int i = 0; i < 8; i++) row_acc[i] = 0.f;

    for (int tc = 0; tc < NTILES; tc++) {
        __syncthreads();
        for (int idx = tid; idx < TN * 8; idx += 256) {
            int r  = idx >> 3;
            int kq = (idx & 7) * 4;
            float4 v4 = *(const float4*)&Y[(size_t)(tc * TN + r) * DK + kq];
            Ys[kq + 0][r] = v4.x; Ys[kq + 1][r] = v4.y;
            Ys[kq + 2][r] = v4.z; Ys[kq + 3][r] = v4.w;
        }
        __syncthreads();

        ull acc2[8][4];
#pragma unroll
        for (int i = 0; i < 8; i++)
#pragma unroll
            for (int c = 0; c < 4; c++) acc2[i][c] = 0ull;

#pragma unroll 8
        for (int k = 0; k < DK; k++) {
            float4 xv0 = *(const float4*)&Xs[k][ty * 8];
            float4 xv1 = *(const float4*)&Xs[k][ty * 8 + 4];
            float4 yv0 = *(const float4*)&Ys[k][tx * 8];
            float4 yv1 = *(const float4*)&Ys[k][tx * 8 + 4];
            ull xa2[8];
            xa2[0] = splat2(xv0.x); xa2[1] = splat2(xv0.y);
            xa2[2] = splat2(xv0.z); xa2[3] = splat2(xv0.w);
            xa2[4] = splat2(xv1.x); xa2[5] = splat2(xv1.y);
            xa2[6] = splat2(xv1.z); xa2[7] = splat2(xv1.w);
            ull yb2[4];
            yb2[0] = pack2(yv0.x, yv0.y); yb2[1] = pack2(yv0.z, yv0.w);
            yb2[2] = pack2(yv1.x, yv1.y); yb2[3] = pack2(yv1.z, yv1.w);
#pragma unroll
            for (int i = 0; i < 8; i++)
#pragma unroll
                for (int c = 0; c < 4; c++)
                    fma2(acc2[i][c], xa2[i], yb2[c]);
        }

        // exp once, feed both reductions (|dot| small -> fp32-safe, no max pass)
        float cp[8];
#pragma unroll
        for (int c = 0; c < 8; c++) cp[c] = 0.f;
#pragma unroll
        for (int i = 0; i < 8; i++)
#pragma unroll
            for (int c = 0; c < 4; c++) {
                float lo, hi;
                unpack2(acc2[i][c], lo, hi);
                float e0 = __expf(lo);
                float e1 = __expf(hi);
                row_acc[i]    += e0 + e1;
                cp[2 * c]     += e0;
                cp[2 * c + 1] += e1;
            }

        // reduce column partials over ty
#pragma unroll
        for (int c = 0; c < 8; c++) red[ty][tx * 8 + c] = cp[c];
        __syncthreads();
        if (tid < TN) {
            float s = 0.f;
#pragma unroll
            for (int t = 0; t < 16; t++) s += red[t][tid];
            g_colpart[p][b][tileR][tc * TN + tid] = s;
        }
    }

    // reduce row sums over tx
    __syncthreads();
#pragma unroll
    for (int i = 0; i < 8; i++) red[tx][ty * 8 + i] = row_acc[i];
    __syncthreads();
    if (tid < TM) {
        float s = 0.f;
#pragma unroll
        for (int t = 0; t < 16; t++) s += red[t][tid];
        g_rowsum[2 * p][b][tileR * TM + tid] = s;
    }
}

// ---------------------------------------------------------------------------
// Kernel 2: deterministic reduction of column-sum partials.
// ---------------------------------------------------------------------------
__global__ void reduce_colpart_kernel()
{
    int idx = blockIdx.x * 256 + threadIdx.x;
    if (idx >= 3 * BSZ * U) return;
    int j   = idx & (U - 1);
    int rem = idx / U;
    int b   = rem & (BSZ - 1);
    int p   = rem / BSZ;
    float s = 0.f;
#pragma unroll
    for (int t = 0; t < NTILES; t++) s += g_colpart[p][b][t][j];
    g_rowsum[2 * p + 1][b][j] = s;
}

// ---------------------------------------------------------------------------
// Kernel 3: finalize Bi rows. One CTA per (batch, pair).
// ---------------------------------------------------------------------------
__global__ __launch_bounds__(256) void finalize_kernel(const float* __restrict__ A,
                                                       const float* __restrict__ V,
                                                       const float* __restrict__ L)
{
    const int b = blockIdx.x;
    const int p = blockIdx.y;
    const float *X, *Y;
    if (p == 0)      { X = A; Y = V; }
    else if (p == 1) { X = A; Y = L; }
    else             { X = V; Y = L; }
    X += (size_t)b * U * DK;
    Y += (size_t)b * U * DK;

    __shared__ float X0[32], Y0[32];
    __shared__ float sred[8][64];

    const int tid = threadIdx.x;
    if (tid < 32)      X0[tid]      = X[tid];
    else if (tid < 64) Y0[tid - 32] = Y[tid - 32];
    __syncthreads();

    float O1[32], O2[32];
#pragma unroll
    for (int d = 0; d < 32; d++) { O1[d] = 0.f; O2[d] = 0.f; }

    for (int j = tid; j < U; j += 256) {
        float xj[32], yj[32];
#pragma unroll
        for (int q = 0; q < 8; q++) {
            float4 v = *(const float4*)&Y[(size_t)j * DK + q * 4];
            yj[q*4+0] = v.x; yj[q*4+1] = v.y; yj[q*4+2] = v.z; yj[q*4+3] = v.w;
            float4 w = *(const float4*)&X[(size_t)j * DK + q * 4];
            xj[q*4+0] = w.x; xj[q*4+1] = w.y; xj[q*4+2] = w.z; xj[q*4+3] = w.w;
        }
        float d1 = 0.f, d2 = 0.f;
#pragma unroll
        for (int k = 0; k < 32; k++) {
            d1 = fmaf(X0[k], yj[k], d1);
            d2 = fmaf(xj[k], Y0[k], d2);
        }
        float w1 = __expf(d1) / g_rowsum[2 * p + 1][b][j];
        float w2 = __expf(d2) / g_rowsum[2 * p][b][j];
#pragma unroll
        for (int k = 0; k < 32; k++) {
            O1[k] = fmaf(w1, yj[k], O1[k]);
            O2[k] = fmaf(w2, xj[k], O2[k]);
        }
    }

#pragma unroll
    for (int k = 0; k < 32; k++) {
        for (int o = 16; o > 0; o >>= 1) {
            O1[k] += __shfl_down_sync(0xffffffffu, O1[k], o);
            O2[k] += __shfl_down_sync(0xffffffffu, O2[k], o);
        }
    }
    const int w    = tid >> 5;
    const int lane = tid & 31;
    if (lane == 0) {
#pragma unroll
        for (int k = 0; k < 32; k++) {
            sred[w][k]      = O1[k];
            sred[w][k + 32] = O2[k];
        }
    }
    __syncthreads();
    if (tid < 64) {
        float s = 0.f;
#pragma unroll
        for (int t = 0; t < 8; t++) s += sred[t][tid];
        float a = (tid < 32) ? X0[tid] : Y0[tid - 32];
        g_Bi[b][p][tid] = s * a;
    }
}

// ---------------------------------------------------------------------------
// Kernel 4: FC head + batch softmax + combine. One warp per (b,k) pair,
// lanes parallel over the 64 hidden units.  (Was 183us serial on 2 warps.)
// ---------------------------------------------------------------------------
__global__ __launch_bounds__(1024) void head_kernel(const float* __restrict__ fc1w,
                                                    const float* __restrict__ fc1b,
                                                    const float* __restrict__ fc2w)
{
    __shared__ float Ci[48];
    __shared__ float colsum[3];
    const int tid  = threadIdx.x;
    const int warp = tid >> 5;
    const int lane = tid & 31;

    for (int pr = warp; pr < 48; pr += 32) {
        const int b = pr / 3, k = pr % 3;
        const float* row = g_Bi[b][k];
        float ci = 0.f;
#pragma unroll
        for (int half = 0; half < 2; half++) {
            const int o = lane + 32 * half;
            float h = fc1b[o];
#pragma unroll 8
            for (int m = 0; m < 64; m++) h = fmaf(row[m], fc1w[o * 64 + m], h);
            ci += tanhf(h) * fc2w[o];
        }
#pragma unroll
        for (int o = 16; o > 0; o >>= 1) ci += __shfl_down_sync(0xffffffffu, ci, o);
        if (lane == 0) Ci[pr] = ci;
    }
    __syncthreads();
    if (tid < 3) {
        float s = 0.f;
        for (int b = 0; b < 16; b++) s += expf(Ci[b * 3 + tid]);
        colsum[tid] = s;
    }
    __syncthreads();
    if (tid < 64) {
        for (int b = 0; b < 16; b++) {
            float s = 0.f;
#pragma unroll
            for (int k = 0; k < 3; k++) {
                float alpha = expf(Ci[b * 3 + k]) / colsum[k];
                s += alpha * g_Bi[b][k][tid];
            }
            g_row[b][tid] = s;
        }
    }
}

// ---------------------------------------------------------------------------
// Kernel 5: broadcast per-batch row to [B, U, 64].
// ---------------------------------------------------------------------------
__global__ void bcast_kernel(float4* __restrict__ out)
{
    int i = blockIdx.x * 256 + threadIdx.x;      // float4 index
    if (i >= BSZ * U * 16) return;
    int d4  = i & 15;
    int u_b = i >> 4;
    int b   = u_b >> 11;
    out[i] = ((const float4*)g_row)[b * 16 + d4];
}

// ---------------------------------------------------------------------------
extern "C" void kernel_launch(void* const* d_in, const int* in_sizes, int n_in,
                              void* d_out, int out_size)
{
    const float* A    = (const float*)d_in[0];
    const float* V    = (const float*)d_in[1];
    const float* L    = (const float*)d_in[2];
    const float* fc1w = (const float*)d_in[3];
    const float* fc1b = (const float*)d_in[4];
    const float* fc2w = (const float*)d_in[5];

    dim3 g1(NTILES, BSZ, 3);
    gram_kernel<<<g1, 256>>>(A, V, L);
    reduce_colpart_kernel<<<(3 * BSZ * U + 255) / 256, 256>>>();
    finalize_kernel<<<dim3(BSZ, 3), 256>>>(A, V, L);
    head_kernel<<<1, 1024>>>(fc1w, fc1b, fc2w);
    bcast_kernel<<<(BSZ * U * 16 + 255) / 256, 256>>>((float4*)d_out);
}

// round 9
// speedup vs baseline: 1.4325x; 1.2636x over previous
#include <cuda_runtime.h>

#define U   2048
#define BSZ 16
#define DK  32
#define TM  128
#define TN  128
#define NTILES (U / TM)   // 16
#define LOG2E 1.4426950408889634f

typedef unsigned long long ull;

// Scratch (static __device__ — no allocation allowed)
__device__ float g_rowsum[6][BSZ][U];              // directed row sums
__device__ float g_colpart[3][BSZ][NTILES][U];     // per-row-tile partial column sums
__device__ float g_Bi[BSZ][3][64];                 // Bi rows
__device__ float g_row[BSZ][64];                   // final per-batch CCA row

// ---- packed f32x2 helpers (sm_103a) ---------------------------------------
__device__ __forceinline__ ull splat2(float x) {
    ull r; asm("mov.b64 %0, {%1, %1};" : "=l"(r) : "f"(x)); return r;
}
__device__ __forceinline__ ull pack2(float lo, float hi) {
    ull r; asm("mov.b64 %0, {%1, %2};" : "=l"(r) : "f"(lo), "f"(hi)); return r;
}
__device__ __forceinline__ void fma2(ull &d, ull a, ull b) {
    asm("fma.rn.f32x2 %0, %1, %2, %0;" : "+l"(d) : "l"(a), "l"(b));
}
__device__ __forceinline__ void add2(ull &d, ull a) {
    asm("add.rn.f32x2 %0, %0, %1;" : "+l"(d) : "l"(a));
}
__device__ __forceinline__ void unpack2(ull v, float &lo, float &hi) {
    asm("mov.b64 {%0, %1}, %2;" : "=f"(lo), "=f"(hi) : "l"(v));
}
__device__ __forceinline__ float ex2(float x) {
    float r; asm("ex2.approx.f32 %0, %1;" : "=f"(r) : "f"(x)); return r;
}

// ---------------------------------------------------------------------------
// Kernel 1: fused gram + exp + dual reduction (FFMA2 mainloop, EX2 epilogue).
// X staged pre-scaled by log2(e) so exp(dot) == ex2(acc): no epilogue FMUL.
// ---------------------------------------------------------------------------
__global__ __launch_bounds__(256) void gram_kernel(const float* __restrict__ A,
                                                   const float* __restrict__ V,
                                                   const float* __restrict__ L)
{
    const int tileR = blockIdx.x;
    const int b     = blockIdx.y;
    const int p     = blockIdx.z;

    const float *X, *Y;
    if (p == 0)      { X = A; Y = V; }
    else if (p == 1) { X = A; Y = L; }
    else             { X = V; Y = L; }
    X += (size_t)b * U * DK;
    Y += (size_t)b * U * DK;

    __shared__ float Xs[DK][TM];        // k-major, pre-scaled by log2(e)
    __shared__ float Ys[DK][TN];
    __shared__ float red[16][TN + 8];

    const int tid = threadIdx.x;
    const int tx  = tid & 15;
    const int ty  = tid >> 4;

    // Load X row tile (transpose to k-major, scale by log2e)
    for (int idx = tid; idx < TM * 8; idx += 256) {
        int r  = idx >> 3;
        int kq = (idx & 7) * 4;
        float4 v4 = *(const float4*)&X[(size_t)(tileR * TM + r) * DK + kq];
        Xs[kq + 0][r] = v4.x * LOG2E; Xs[kq + 1][r] = v4.y * LOG2E;
        Xs[kq + 2][r] = v4.z * LOG2E; Xs[kq + 3][r] = v4.w * LOG2E;
    }

    ull rowp[8];                         // packed row-sum accumulators
#pragma unroll
    for (int i = 0; i < 8; i++) rowp[i] = 0ull;

    for (int tc = 0; tc < NTILES; tc++) {
        __syncthreads();
        for (int idx = tid; idx < TN * 8; idx += 256) {
            int r  = idx >> 3;
            int kq = (idx & 7) * 4;
            float4 v4 = *(const float4*)&Y[(size_t)(tc * TN + r) * DK + kq];
            Ys[kq + 0][r] = v4.x; Ys[kq + 1][r] = v4.y;
            Ys[kq + 2][r] = v4.z; Ys[kq + 3][r] = v4.w;
        }
        __syncthreads();

        ull acc2[8][4];
#pragma unroll
        for (int i = 0; i < 8; i++)
#pragma unroll
            for (int c = 0; c < 4; c++) acc2[i][c] = 0ull;

#pragma unroll 8
        for (int k = 0; k < DK; k++) {
            float4 xv0 = *(const float4*)&Xs[k][ty * 8];
            float4 xv1 = *(const float4*)&Xs[k][ty * 8 + 4];
            float4 yv0 = *(const float4*)&Ys[k][tx * 8];
            float4 yv1 = *(const float4*)&Ys[k][tx * 8 + 4];
            ull xa2[8];
            xa2[0] = splat2(xv0.x); xa2[1] = splat2(xv0.y);
            xa2[2] = splat2(xv0.z); xa2[3] = splat2(xv0.w);
            xa2[4] = splat2(xv1.x); xa2[5] = splat2(xv1.y);
            xa2[6] = splat2(xv1.z); xa2[7] = splat2(xv1.w);
            ull yb2[4];
            yb2[0] = pack2(yv0.x, yv0.y); yb2[1] = pack2(yv0.z, yv0.w);
            yb2[2] = pack2(yv1.x, yv1.y); yb2[3] = pack2(yv1.z, yv1.w);
#pragma unroll
            for (int i = 0; i < 8; i++)
#pragma unroll
                for (int c = 0; c < 4; c++)
                    fma2(acc2[i][c], xa2[i], yb2[c]);
        }

        // exp2 once (acc already carries log2e), packed dual reduction
        ull cp2[4];
#pragma unroll
        for (int c = 0; c < 4; c++) cp2[c] = 0ull;
#pragma unroll
        for (int i = 0; i < 8; i++)
#pragma unroll
            for (int c = 0; c < 4; c++) {
                float lo, hi;
                unpack2(acc2[i][c], lo, hi);
                ull e = pack2(ex2(lo), ex2(hi));
                add2(rowp[i], e);
                add2(cp2[c], e);
            }

        // reduce column partials over ty
#pragma unroll
        for (int c = 0; c < 4; c++) {
            float lo, hi;
            unpack2(cp2[c], lo, hi);
            red[ty][tx * 8 + 2 * c]     = lo;
            red[ty][tx * 8 + 2 * c + 1] = hi;
        }
        __syncthreads();
        if (tid < TN) {
            float s = 0.f;
#pragma unroll
            for (int t = 0; t < 16; t++) s += red[t][tid];
            g_colpart[p][b][tileR][tc * TN + tid] = s;
        }
    }

    // reduce row sums over tx
    __syncthreads();
#pragma unroll
    for (int i = 0; i < 8; i++) {
        float lo, hi;
        unpack2(rowp[i], lo, hi);
        red[tx][ty * 8 + i] = lo + hi;
    }
    __syncthreads();
    if (tid < TM) {
        float s = 0.f;
#pragma unroll
        for (int t = 0; t < 16; t++) s += red[t][tid];
        g_rowsum[2 * p][b][tileR * TM + tid] = s;
    }
}

// ---------------------------------------------------------------------------
// Kernel 2: deterministic reduction of column-sum partials.
// ---------------------------------------------------------------------------
__global__ void reduce_colpart_kernel()
{
    int idx = blockIdx.x * 256 + threadIdx.x;
    if (idx >= 3 * BSZ * U) return;
    int j   = idx & (U - 1);
    int rem = idx / U;
    int b   = rem & (BSZ - 1);
    int p   = rem / BSZ;
    float s = 0.f;
#pragma unroll
    for (int t = 0; t < NTILES; t++) s += g_colpart[p][b][t][j];
    g_rowsum[2 * p + 1][b][j] = s;
}

// ---------------------------------------------------------------------------
// Kernel 3: finalize Bi rows. One CTA per (batch, pair).
// ---------------------------------------------------------------------------
__global__ __launch_bounds__(256) void finalize_kernel(const float* __restrict__ A,
                                                       const float* __restrict__ V,
                                                       const float* __restrict__ L)
{
    const int b = blockIdx.x;
    const int p = blockIdx.y;
    const float *X, *Y;
    if (p == 0)      { X = A; Y = V; }
    else if (p == 1) { X = A; Y = L; }
    else             { X = V; Y = L; }
    X += (size_t)b * U * DK;
    Y += (size_t)b * U * DK;

    __shared__ float X0[32], Y0[32];
    __shared__ float sred[8][64];

    const int tid = threadIdx.x;
    if (tid < 32)      X0[tid]      = X[tid];
    else if (tid < 64) Y0[tid - 32] = Y[tid - 32];
    __syncthreads();

    float O1[32], O2[32];
#pragma unroll
    for (int d = 0; d < 32; d++) { O1[d] = 0.f; O2[d] = 0.f; }

    for (int j = tid; j < U; j += 256) {
        float xj[32], yj[32];
#pragma unroll
        for (int q = 0; q < 8; q++) {
            float4 v = *(const float4*)&Y[(size_t)j * DK + q * 4];
            yj[q*4+0] = v.x; yj[q*4+1] = v.y; yj[q*4+2] = v.z; yj[q*4+3] = v.w;
            float4 w = *(const float4*)&X[(size_t)j * DK + q * 4];
            xj[q*4+0] = w.x; xj[q*4+1] = w.y; xj[q*4+2] = w.z; xj[q*4+3] = w.w;
        }
        float d1 = 0.f, d2 = 0.f;
#pragma unroll
        for (int k = 0; k < 32; k++) {
            d1 = fmaf(X0[k], yj[k], d1);
            d2 = fmaf(xj[k], Y0[k], d2);
        }
        float w1 = ex2(d1 * LOG2E) / g_rowsum[2 * p + 1][b][j];
        float w2 = ex2(d2 * LOG2E) / g_rowsum[2 * p][b][j];
#pragma unroll
        for (int k = 0; k < 32; k++) {
            O1[k] = fmaf(w1, yj[k], O1[k]);
            O2[k] = fmaf(w2, xj[k], O2[k]);
        }
    }

#pragma unroll
    for (int k = 0; k < 32; k++) {
        for (int o = 16; o > 0; o >>= 1) {
            O1[k] += __shfl_down_sync(0xffffffffu, O1[k], o);
            O2[k] += __shfl_down_sync(0xffffffffu, O2[k], o);
        }
    }
    const int w    = tid >> 5;
    const int lane = tid & 31;
    if (lane == 0) {
#pragma unroll
        for (int k = 0; k < 32; k++) {
            sred[w][k]      = O1[k];
            sred[w][k + 32] = O2[k];
        }
    }
    __syncthreads();
    if (tid < 64) {
        float s = 0.f;
#pragma unroll
        for (int t = 0; t < 8; t++) s += sred[t][tid];
        float a = (tid < 32) ? X0[tid] : Y0[tid - 32];
        g_Bi[b][p][tid] = s * a;
    }
}

// ---------------------------------------------------------------------------
// Kernel 4: FC head. fc1w staged TRANSPOSED in smem (the 106us was all
// uncoalesced fc1w wavefronts on one SM). One warp per (b,k), lanes over
// hidden units, row broadcast via shuffle.
// ---------------------------------------------------------------------------
__global__ __launch_bounds__(1024) void head_kernel(const float* __restrict__ fc1w,
                                                    const float* __restrict__ fc1b,
                                                    const float* __restrict__ fc2w)
{
    __shared__ float Wt[64][64];   // Wt[m][o] = fc1w[o][m]
    __shared__ float Ci[48];
    __shared__ float colsum[3];
    const int tid  = threadIdx.x;
    const int warp = tid >> 5;
    const int lane = tid & 31;

    // coalesced gmem read, transposed smem write (one-time 16 KB)
    for (int i = tid; i < 64 * 64; i += 1024) {
        int o = i >> 6, m = i & 63;
        Wt[m][o] = fc1w[i];
    }
    __syncthreads();

    for (int pr = warp; pr < 48; pr += 32) {
        const int b = pr / 3, k = pr % 3;
        float r0 = g_Bi[b][k][lane];
        float r1 = g_Bi[b][k][lane + 32];
        float h0 = fc1b[lane];
        float h1 = fc1b[lane + 32];
#pragma unroll 8
        for (int m = 0; m < 32; m++) {
            float rm = __shfl_sync(0xffffffffu, r0, m);
            h0 = fmaf(rm, Wt[m][lane],      h0);
            h1 = fmaf(rm, Wt[m][lane + 32], h1);
        }
#pragma unroll 8
        for (int m = 0; m < 32; m++) {
            float rm = __shfl_sync(0xffffffffu, r1, m);
            h0 = fmaf(rm, Wt[m + 32][lane],      h0);
            h1 = fmaf(rm, Wt[m + 32][lane + 32], h1);
        }
        float ci = tanhf(h0) * fc2w[lane] + tanhf(h1) * fc2w[lane + 32];
#pragma unroll
        for (int o = 16; o > 0; o >>= 1) ci += __shfl_down_sync(0xffffffffu, ci, o);
        if (lane == 0) Ci[pr] = ci;
    }
    __syncthreads();
    if (tid < 3) {
        float s = 0.f;
        for (int b = 0; b < 16; b++) s += expf(Ci[b * 3 + tid]);
        colsum[tid] = s;
    }
    __syncthreads();
    if (tid < 64) {
        for (int b = 0; b < 16; b++) {
            float s = 0.f;
#pragma unroll
            for (int k = 0; k < 3; k++) {
                float alpha = expf(Ci[b * 3 + k]) / colsum[k];
                s += alpha * g_Bi[b][k][tid];
            }
            g_row[b][tid] = s;
        }
    }
}

// ---------------------------------------------------------------------------
// Kernel 5: broadcast per-batch row to [B, U, 64].
// ---------------------------------------------------------------------------
__global__ void bcast_kernel(float4* __restrict__ out)
{
    int i = blockIdx.x * 256 + threadIdx.x;      // float4 index
    if (i >= BSZ * U * 16) return;
    int d4  = i & 15;
    int u_b = i >> 4;
    int b   = u_b >> 11;
    out[i] = ((const float4*)g_row)[b * 16 + d4];
}

// ---------------------------------------------------------------------------
extern "C" void kernel_launch(void* const* d_in, const int* in_sizes, int n_in,
                              void* d_out, int out_size)
{
    const float* A    = (const float*)d_in[0];
    const float* V    = (const float*)d_in[1];
    const float* L    = (const float*)d_in[2];
    const float* fc1w = (const float*)d_in[3];
    const float* fc1b = (const float*)d_in[4];
    const float* fc2w = (const float*)d_in[5];

    dim3 g1(NTILES, BSZ, 3);
    gram_kernel<<<g1, 256>>>(A, V, L);
    reduce_colpart_kernel<<<(3 * BSZ * U + 255) / 256, 256>>>();
    finalize_kernel<<<dim3(BSZ, 3), 256>>>(A, V, L);
    head_kernel<<<1, 1024>>>(fc1w, fc1b, fc2w);
    bcast_kernel<<<(BSZ * U * 16 + 255) / 256, 256>>>((float4*)d_out);
}

// round 12
// speedup vs baseline: 3.1080x; 2.1696x over previous
#include <cuda_runtime.h>
#include <cuda_bf16.h>

#define U   2048
#define BSZ 16
#define DK  32
#define TM  128
#define TN  128
#define NTILES (U / TM)   // 16
#define NCTILES (U / TN)  // 16
#define LOG2E 1.4426950408889634f
#define PITCH 80          // smem row pitch (bytes): 64B data + 16B pad -> LDSM conflict-free

// Scratch (static __device__ — no allocation allowed)
__device__ float g_rowsum[6][BSZ][U];
__device__ float g_colpart[3][BSZ][NTILES][U];
__device__ float g_Bi[BSZ][3][64];
__device__ float g_row[BSZ][64];

// ---- helpers ---------------------------------------------------------------
__device__ __forceinline__ float ex2(float x) {
    float r; asm("ex2.approx.f32 %0, %1;" : "=f"(r) : "f"(x)); return r;
}
__device__ __forceinline__ unsigned smem_u32(const void* p) {
    unsigned a;
    asm("{ .reg .u64 t; cvta.to.shared.u64 t, %1; cvt.u32.u64 %0, t; }" : "=r"(a) : "l"(p));
    return a;
}
__device__ __forceinline__ unsigned bf2u(float a, float b) {
    __nv_bfloat162 t = __floats2bfloat162_rn(a, b);
    return *reinterpret_cast<unsigned*>(&t);
}

#define LDSM4(r, a) \
    asm volatile("ldmatrix.sync.aligned.m8n8.x4.shared.b16 {%0,%1,%2,%3}, [%4];" \
        : "=r"((r)[0]), "=r"((r)[1]), "=r"((r)[2]), "=r"((r)[3]) : "r"(a))

#define MMA16816(d, a, b0, b1) \
    asm volatile("mma.sync.aligned.m16n8k16.row.col.f32.bf16.bf16.f32 " \
        "{%0,%1,%2,%3}, {%4,%5,%6,%7}, {%8,%9}, {%0,%1,%2,%3};" \
        : "+f"((d)[0]), "+f"((d)[1]), "+f"((d)[2]), "+f"((d)[3]) \
        : "r"((a)[0]), "r"((a)[1]), "r"((a)[2]), "r"((a)[3]), "r"(b0), "r"(b1))

// ---------------------------------------------------------------------------
// Kernel 1: gram via mma.sync (bf16 hh+hl+lh fp32 emulation) + EX2 + dual
// (row/col) reduction straight from register D-fragments.
// grid = (rowTile, batch, pair); CTA = 8 warps as 4(M)x2(N); warp tile 32x64.
// ---------------------------------------------------------------------------
__global__ __launch_bounds__(256, 2) void gram_kernel(const float* __restrict__ A,
                                                      const float* __restrict__ V,
                                                      const float* __restrict__ L)
{
    __shared__ __align__(16) unsigned char sXhi[TM * PITCH];
    __shared__ __align__(16) unsigned char sXlo[TM * PITCH];
    __shared__ __align__(16) unsigned char sYhi[TN * PITCH];
    __shared__ __align__(16) unsigned char sYlo[TN * PITCH];
    __shared__ float colred[4][128];
    __shared__ float rowred[2][128];

    const int tileR = blockIdx.x;
    const int b     = blockIdx.y;
    const int p     = blockIdx.z;

    const float *X, *Y;
    if (p == 0)      { X = A; Y = V; }
    else if (p == 1) { X = A; Y = L; }
    else             { X = V; Y = L; }
    X += (size_t)b * U * DK;
    Y += (size_t)b * U * DK;

    const int tid  = threadIdx.x;
    const int warp = tid >> 5;
    const int lane = tid & 31;
    const int wr   = warp >> 1;   // 0..3 : M position (rows wr*32..+31)
    const int wc   = warp & 1;    // 0..1 : N position (cols wc*64..+63)

    // ---- stage X once: bf16 hi/lo split, pre-scaled by log2(e) ----
    for (int it = 0; it < 4; it++) {
        int idx = tid + it * 256;           // 0..1023
        int r   = idx >> 3;
        int kq  = (idx & 7) * 4;
        float4 v = *(const float4*)&X[(size_t)(tileR * TM + r) * DK + kq];
        v.x *= LOG2E; v.y *= LOG2E; v.z *= LOG2E; v.w *= LOG2E;
        __nv_bfloat16 h0 = __float2bfloat16(v.x), h1 = __float2bfloat16(v.y);
        __nv_bfloat16 h2 = __float2bfloat16(v.z), h3 = __float2bfloat16(v.w);
        float l0 = v.x - __bfloat162float(h0), l1 = v.y - __bfloat162float(h1);
        float l2 = v.z - __bfloat162float(h2), l3 = v.w - __bfloat162float(h3);
        int off = r * PITCH + kq * 2;
        *(unsigned*)&sXhi[off]     = bf2u(__bfloat162float(h0), __bfloat162float(h1));
        *(unsigned*)&sXhi[off + 4] = bf2u(__bfloat162float(h2), __bfloat162float(h3));
        *(unsigned*)&sXlo[off]     = bf2u(l0, l1);
        *(unsigned*)&sXlo[off + 4] = bf2u(l2, l3);
    }
    __syncthreads();

    const unsigned xh_u = smem_u32(sXhi);
    const unsigned xl_u = smem_u32(sXlo);
    const unsigned yh_u = smem_u32(sYhi);
    const unsigned yl_u = smem_u32(sYlo);

    // ---- hoist A fragments (X is invariant across N-tiles) ----
    unsigned Ah[2][2][4], Al[2][2][4];
#pragma unroll
    for (int mi = 0; mi < 2; mi++)
#pragma unroll
        for (int kh = 0; kh < 2; kh++) {
            unsigned row  = wr * 32 + mi * 16 + (lane & 15);
            unsigned byte = kh * 32 + ((lane & 16) ? 16u : 0u);
            LDSM4(Ah[mi][kh], xh_u + row * PITCH + byte);
            LDSM4(Al[mi][kh], xl_u + row * PITCH + byte);
        }

    float rp[4] = {0.f, 0.f, 0.f, 0.f};   // row-sum partials (mi,half)

    for (int nt = 0; nt < NCTILES; nt++) {
        __syncthreads();   // prev iter: B ldmatrix + colred read done
        // ---- stage Y tile (bf16 hi/lo, unscaled) ----
        for (int it = 0; it < 4; it++) {
            int idx = tid + it * 256;
            int r   = idx >> 3;
            int kq  = (idx & 7) * 4;
            float4 v = *(const float4*)&Y[(size_t)(nt * TN + r) * DK + kq];
            __nv_bfloat16 h0 = __float2bfloat16(v.x), h1 = __float2bfloat16(v.y);
            __nv_bfloat16 h2 = __float2bfloat16(v.z), h3 = __float2bfloat16(v.w);
            float l0 = v.x - __bfloat162float(h0), l1 = v.y - __bfloat162float(h1);
            float l2 = v.z - __bfloat162float(h2), l3 = v.w - __bfloat162float(h3);
            int off = r * PITCH + kq * 2;
            *(unsigned*)&sYhi[off]     = bf2u(__bfloat162float(h0), __bfloat162float(h1));
            *(unsigned*)&sYhi[off + 4] = bf2u(__bfloat162float(h2), __bfloat162float(h3));
            *(unsigned*)&sYlo[off]     = bf2u(l0, l1);
            *(unsigned*)&sYlo[off + 4] = bf2u(l2, l3);
        }
        __syncthreads();

        // ---- MMA: D = Xhi*Yhi + Xhi*Ylo + Xlo*Yhi ----
        float d[2][8][4];
#pragma unroll
        for (int mi = 0; mi < 2; mi++)
#pragma unroll
            for (int nn = 0; nn < 8; nn++)
#pragma unroll
                for (int c = 0; c < 4; c++) d[mi][nn][c] = 0.f;

#pragma unroll
        for (int nc = 0; nc < 4; nc++) {
            // ldmatrix x4 address: m0 = n rows nb+0..7 (k low 16B), m1 = same rows +16B,
            // m2/m3 = n rows nb+8..15  ->  (b0,b1) n8-frag 0, (b2,b3) n8-frag 1
            unsigned mm   = (unsigned)lane >> 3;
            unsigned brow = wc * 64 + nc * 16 + ((mm & 2) ? 8u : 0u) + (lane & 7);
#pragma unroll
            for (int kh = 0; kh < 2; kh++) {
                unsigned byte = kh * 32 + (mm & 1) * 16;
                unsigned bh[4], bl[4];
                LDSM4(bh, yh_u + brow * PITCH + byte);
                LDSM4(bl, yl_u + brow * PITCH + byte);
#pragma unroll
                for (int mi = 0; mi < 2; mi++) {
                    MMA16816(d[mi][2 * nc],     Ah[mi][kh], bh[0], bh[1]);
                    MMA16816(d[mi][2 * nc + 1], Ah[mi][kh], bh[2], bh[3]);
                    MMA16816(d[mi][2 * nc],     Ah[mi][kh], bl[0], bl[1]);
                    MMA16816(d[mi][2 * nc + 1], Ah[mi][kh], bl[2], bl[3]);
                    MMA16816(d[mi][2 * nc],     Al[mi][kh], bh[0], bh[1]);
                    MMA16816(d[mi][2 * nc + 1], Al[mi][kh], bh[2], bh[3]);
                }
            }
        }

        // ---- epilogue: exp2 once, row partials in regs, col sums via shfl ----
#pragma unroll
        for (int nn = 0; nn < 8; nn++) {
            float c0 = 0.f, c1 = 0.f;
#pragma unroll
            for (int mi = 0; mi < 2; mi++) {
                float e0 = ex2(d[mi][nn][0]);
                float e1 = ex2(d[mi][nn][1]);
                float e2 = ex2(d[mi][nn][2]);
                float e3 = ex2(d[mi][nn][3]);
                rp[mi * 2 + 0] += e0 + e1;     // row g     (lane>>2)
                rp[mi * 2 + 1] += e2 + e3;     // row g + 8
                c0 += e0 + e2;
                c1 += e1 + e3;
            }
            // sum over the 8 lane-groups (rows) sharing this column pair
            c0 += __shfl_xor_sync(0xffffffffu, c0, 4);
            c0 += __shfl_xor_sync(0xffffffffu, c0, 8);
            c0 += __shfl_xor_sync(0xffffffffu, c0, 16);
            c1 += __shfl_xor_sync(0xffffffffu, c1, 4);
            c1 += __shfl_xor_sync(0xffffffffu, c1, 8);
            c1 += __shfl_xor_sync(0xffffffffu, c1, 16);
            if (lane < 4) {
                int col = wc * 64 + nn * 8 + lane * 2;
                colred[wr][col]     = c0;
                colred[wr][col + 1] = c1;
            }
        }
        __syncthreads();
        if (tid < 128) {
            float s = (colred[0][tid] + colred[1][tid]) + (colred[2][tid] + colred[3][tid]);
            g_colpart[p][b][tileR][nt * TN + tid] = s;
        }
    }

    // ---- row sums: reduce over lane column-groups, then across wc ----
#pragma unroll
    for (int i = 0; i < 4; i++) {
        rp[i] += __shfl_xor_sync(0xffffffffu, rp[i], 1);
        rp[i] += __shfl_xor_sync(0xffffffffu, rp[i], 2);
    }
    if ((lane & 3) == 0) {
        int g = lane >> 2;
        rowred[wc][wr * 32 + 0  + g] = rp[0];
        rowred[wc][wr * 32 + 8  + g] = rp[1];
        rowred[wc][wr * 32 + 16 + g] = rp[2];
        rowred[wc][wr * 32 + 24 + g] = rp[3];
    }
    __syncthreads();
    if (tid < 128)
        g_rowsum[2 * p][b][tileR * TM + tid] = rowred[0][tid] + rowred[1][tid];
}

// ---------------------------------------------------------------------------
// Kernel 2: deterministic reduction of column-sum partials.
// ---------------------------------------------------------------------------
__global__ void reduce_colpart_kernel()
{
    int idx = blockIdx.x * 256 + threadIdx.x;
    if (idx >= 3 * BSZ * U) return;
    int jj  = idx & (U - 1);
    int rem = idx / U;
    int b   = rem & (BSZ - 1);
    int p   = rem / BSZ;
    float s = 0.f;
#pragma unroll
    for (int t = 0; t < NTILES; t++) s += g_colpart[p][b][t][jj];
    g_rowsum[2 * p + 1][b][jj] = s;
}

// ---------------------------------------------------------------------------
// Kernel 3: finalize Bi rows (fp32 numerators). One CTA per (batch, pair).
// ---------------------------------------------------------------------------
__global__ __launch_bounds__(256) void finalize_kernel(const float* __restrict__ A,
                                                       const float* __restrict__ V,
                                                       const float* __restrict__ L)
{
    const int b = blockIdx.x;
    const int p = blockIdx.y;
    const float *X, *Y;
    if (p == 0)      { X = A; Y = V; }
    else if (p == 1) { X = A; Y = L; }
    else             { X = V; Y = L; }
    X += (size_t)b * U * DK;
    Y += (size_t)b * U * DK;

    __shared__ float X0[32], Y0[32];
    __shared__ float sred[8][64];

    const int tid = threadIdx.x;
    if (tid < 32)      X0[tid]      = X[tid];
    else if (tid < 64) Y0[tid - 32] = Y[tid - 32];
    __syncthreads();

    float O1[32], O2[32];
#pragma unroll
    for (int d = 0; d < 32; d++) { O1[d] = 0.f; O2[d] = 0.f; }

    for (int jj = tid; jj < U; jj += 256) {
        float xj[32], yj[32];
#pragma unroll
        for (int qq = 0; qq < 8; qq++) {
            float4 v = *(const float4*)&Y[(size_t)jj * DK + qq * 4];
            yj[qq*4+0] = v.x; yj[qq*4+1] = v.y; yj[qq*4+2] = v.z; yj[qq*4+3] = v.w;
            float4 ww = *(const float4*)&X[(size_t)jj * DK + qq * 4];
            xj[qq*4+0] = ww.x; xj[qq*4+1] = ww.y; xj[qq*4+2] = ww.z; xj[qq*4+3] = ww.w;
        }
        float d1 = 0.f, d2 = 0.f;
#pragma unroll
        for (int k = 0; k < 32; k++) {
            d1 = fmaf(X0[k], yj[k], d1);
            d2 = fmaf(xj[k], Y0[k], d2);
        }
        float w1 = ex2(d1 * LOG2E) / g_rowsum[2 * p + 1][b][jj];
        float w2 = ex2(d2 * LOG2E) / g_rowsum[2 * p][b][jj];
#pragma unroll
        for (int k = 0; k < 32; k++) {
            O1[k] = fmaf(w1, yj[k], O1[k]);
            O2[k] = fmaf(w2, xj[k], O2[k]);
        }
    }

#pragma unroll
    for (int k = 0; k < 32; k++) {
        for (int o = 16; o > 0; o >>= 1) {
            O1[k] += __shfl_down_sync(0xffffffffu, O1[k], o);
            O2[k] += __shfl_down_sync(0xffffffffu, O2[k], o);
        }
    }
    const int w    = tid >> 5;
    const int lane = tid & 31;
    if (lane == 0) {
#pragma unroll
        for (int k = 0; k < 32; k++) {
            sred[w][k]      = O1[k];
            sred[w][k + 32] = O2[k];
        }
    }
    __syncthreads();
    if (tid < 64) {
        float s = 0.f;
#pragma unroll
        for (int t = 0; t < 8; t++) s += sred[t][tid];
        float a = (tid < 32) ? X0[tid] : Y0[tid - 32];
        g_Bi[b][p][tid] = s * a;
    }
}

// ---------------------------------------------------------------------------
// Kernel 4: FC head (fc1w transposed through smem), batch softmax, combine.
// ---------------------------------------------------------------------------
__global__ __launch_bounds__(1024) void head_kernel(const float* __restrict__ fc1w,
                                                    const float* __restrict__ fc1b,
                                                    const float* __restrict__ fc2w)
{
    __shared__ float Wt[64][64];
    __shared__ float Ci[48];
    __shared__ float colsum[3];
    const int tid  = threadIdx.x;
    const int warp = tid >> 5;
    const int lane = tid & 31;

    for (int i = tid; i < 64 * 64; i += 1024) {
        int o = i >> 6, m = i & 63;
        Wt[m][o] = fc1w[i];
    }
    __syncthreads();

    for (int pr = warp; pr < 48; pr += 32) {
        const int b = pr / 3, k = pr % 3;
        float r0 = g_Bi[b][k][lane];
        float r1 = g_Bi[b][k][lane + 32];
        float h0 = fc1b[lane];
        float h1 = fc1b[lane + 32];
#pragma unroll 8
        for (int m = 0; m < 32; m++) {
            float rm = __shfl_sync(0xffffffffu, r0, m);
            h0 = fmaf(rm, Wt[m][lane],      h0);
            h1 = fmaf(rm, Wt[m][lane + 32], h1);
        }
#pragma unroll 8
        for (int m = 0; m < 32; m++) {
            float rm = __shfl_sync(0xffffffffu, r1, m);
            h0 = fmaf(rm, Wt[m + 32][lane],      h0);
            h1 = fmaf(rm, Wt[m + 32][lane + 32], h1);
        }
        float ci = tanhf(h0) * fc2w[lane] + tanhf(h1) * fc2w[lane + 32];
#pragma unroll
        for (int o = 16; o > 0; o >>= 1) ci += __shfl_down_sync(0xffffffffu, ci, o);
        if (lane == 0) Ci[pr] = ci;
    }
    __syncthreads();
    if (tid < 3) {
        float s = 0.f;
        for (int b = 0; b < 16; b++) s += expf(Ci[b * 3 + tid]);
        colsum[tid] = s;
    }
    __syncthreads();
    if (tid < 64) {
        for (int b = 0; b < 16; b++) {
            float s = 0.f;
#pragma unroll
            for (int k = 0; k < 3; k++) {
                float alpha = expf(Ci[b * 3 + k]) / colsum[k];
                s += alpha * g_Bi[b][k][tid];
            }
            g_row[b][tid] = s;
        }
    }
}

// ---------------------------------------------------------------------------
// Kernel 5: broadcast per-batch row to [B, U, 64].
// ---------------------------------------------------------------------------
__global__ void bcast_kernel(float4* __restrict__ out)
{
    int i = blockIdx.x * 256 + threadIdx.x;
    if (i >= BSZ * U * 16) return;
    int d4  = i & 15;
    int u_b = i >> 4;
    int b   = u_b >> 11;
    out[i] = ((const float4*)g_row)[b * 16 + d4];
}

// ---------------------------------------------------------------------------
extern "C" void kernel_launch(void* const* d_in, const int* in_sizes, int n_in,
                              void* d_out, int out_size)
{
    const float* A    = (const float*)d_in[0];
    const float* V    = (const float*)d_in[1];
    const float* L    = (const float*)d_in[2];
    const float* fc1w = (const float*)d_in[3];
    const float* fc1b = (const float*)d_in[4];
    const float* fc2w = (const float*)d_in[5];

    dim3 g1(NTILES, BSZ, 3);
    gram_kernel<<<g1, 256>>>(A, V, L);
    reduce_colpart_kernel<<<(3 * BSZ * U + 255) / 256, 256>>>();
    finalize_kernel<<<dim3(BSZ, 3), 256>>>(A, V, L);
    head_kernel<<<1, 1024>>>(fc1w, fc1b, fc2w);
    bcast_kernel<<<(BSZ * U * 16 + 255) / 256, 256>>>((float4*)d_out);
}